// round 10
// baseline (speedup 1.0000x reference)
#include <cuda_runtime.h>
#include <math.h>
#include <stdint.h>

#define D_ 256
#define H_ 256
#define B_ 128
#define E_ 128
#define STEPS_ 5
#define NMAX 100352
#define P_ 8            // attention partials per segment

// ---------------- scratch ----------------
__device__ __align__(16) float g_hfeat[NMAX * H_];
__device__ __align__(16) float g_gpart[2 * B_ * 4 * H_];
__device__ float g_hbuf[2][3][B_ * H_];
__device__ float g_c[3][B_ * H_];
__device__ float g_qstar[B_ * 2 * H_];
__device__ int   g_seg[B_ + 1];
__device__ __align__(16) float g_Wt1[D_ * H_];
__device__ __align__(16) float g_Wt2[H_ * H_];
__device__ float g_att_m[B_ * P_];
__device__ float g_att_d[B_ * P_];
__device__ __align__(16) float g_att_acc[B_ * P_ * H_];

__device__ __forceinline__ uint32_t cvt_tf32(float f) {
    uint32_t r;
    asm("cvt.rn.tf32.f32 %0, %1;" : "=r"(r) : "f"(f));
    return r;
}

// ---------------- init + segment offsets (merged) ----------------
__global__ void k_initseg(const int* __restrict__ idx, int N) {
    if (blockIdx.x == 0) {
        int b = threadIdx.x;
        if (b <= B_) {
            int lo = 0, hi = N;
            while (lo < hi) {
                int mid = (lo + hi) >> 1;
                if (idx[mid] < b) lo = mid + 1; else hi = mid;
            }
            g_seg[b] = lo;
        }
    } else {
        int i = (blockIdx.x - 1) * blockDim.x + threadIdx.x;
        int stride = (gridDim.x - 1) * blockDim.x;
        for (int j = i; j < B_ * 2 * H_; j += stride) g_qstar[j] = 0.f;
        for (int j = i; j < 3 * B_ * H_; j += stride) {
            g_hbuf[0][0][j] = 0.f;
            g_hbuf[1][0][j] = 0.f;
            g_c[0][j] = 0.f;
        }
    }
}

// ---------------- weight transpose + tf32 round ----------------
__global__ void k_transpose(const float* __restrict__ W1, const float* __restrict__ W2,
                            float* __restrict__ Wt1, float* __restrict__ Wt2) {
    __shared__ float t[32][33];
    const float* W  = blockIdx.z ? W2  : W1;
    float*       Wt = blockIdx.z ? Wt2 : Wt1;
    int bx = blockIdx.x * 32, by = blockIdx.y * 32;
    int tx = threadIdx.x, ty = threadIdx.y;
    t[ty][tx] = W[(by + ty) * 256 + bx + tx];
    __syncthreads();
    Wt[(bx + ty) * 256 + by + tx] = __uint_as_float(cvt_tf32(t[tx][ty]));
}

// ---------------- fused FNN: GEMM1 -> ELU -> h(smem) -> GEMM2 ----------------
// 1024 threads = 32 warps (wm=warp&3: 4 x 32 rows; wn=warp>>2: 8 x 32 cols).
// Warp tile 32x32, per-thread acc[2][4][4]. XOR-swizzled smem (conflict-free).
#define FH 0
#define FSA 131072
#define FSB 163840
#define FSMEM 229376

#define CP16(dst, src) \
    asm volatile("cp.async.cg.shared.global [%0], [%1], 16;" :: "r"(dst), "l"(src) : "memory")
#define CPCOMMIT() asm volatile("cp.async.commit_group;" ::: "memory")
#define CPWAIT(n)  asm volatile("cp.async.wait_group %0;" :: "n"(n) : "memory")

#define MMA_TF32(d, a, b) \
    asm volatile( \
        "mma.sync.aligned.m16n8k8.row.col.f32.tf32.tf32.f32 " \
        "{%0,%1,%2,%3}, {%4,%5,%6,%7}, {%8,%9}, {%0,%1,%2,%3};" \
        : "+f"((d)[0]), "+f"((d)[1]), "+f"((d)[2]), "+f"((d)[3]) \
        : "r"((a)[0]), "r"((a)[1]), "r"((a)[2]), "r"((a)[3]), \
          "r"((b)[0]), "r"((b)[1]))

__global__ __launch_bounds__(1024, 1) void k_fnn_fused(
    const float* __restrict__ X, const float* __restrict__ W1t,
    const float* __restrict__ W2t, const float* __restrict__ b1,
    const float* __restrict__ b2, float* __restrict__ Cout, int nrows)
{
    extern __shared__ char sm[];
    float* hbuf = (float*)(sm + FH);             // [128][256] swizzled
    __shared__ float bias1[256];
    __shared__ float bias2[256];

    const int tid  = threadIdx.x;
    const int lane = tid & 31;
    const int warp = tid >> 5;
    const int wm = warp & 3;       // m-slab (32 rows)
    const int wn = warp >> 2;      // n-slab (32 cols), 0..7
    const int qr = lane >> 2;
    const int qc = lane & 3;
    const int row0 = blockIdx.x * 128;

    if (tid < 256) bias1[tid] = b1[tid];
    else if (tid < 512) bias2[tid - 256] = b2[tid - 256];

    float acc[2][4][4];
#pragma unroll
    for (int mi = 0; mi < 2; mi++)
#pragma unroll
        for (int ni = 0; ni < 4; ni++)
#pragma unroll
            for (int j = 0; j < 4; j++) acc[mi][ni][j] = 0.f;

    // ---- phase 1: h = ELU(X @ W1t^T + b1), staged A+B, 2-buffer ----
    auto stage1 = [&](int kc, int s) {
        char* dA = sm + FSA + s * 16384;
        char* dB = sm + FSB + s * 32768;
        {
            int r = tid >> 3, g = tid & 7;   // 128 rows x 8 granules, 1/thread
            int gr = row0 + r; if (gr >= nrows) gr = nrows - 1;
            uint32_t dst = (uint32_t)__cvta_generic_to_shared(
                dA + r * 128 + ((g ^ (r & 7)) << 4));
            CP16(dst, X + (size_t)gr * 256 + kc + g * 4);
        }
#pragma unroll
        for (int i = 0; i < 2; i++) {
            int gid = tid + 1024 * i;
            int r = gid >> 3, g = gid & 7;   // 256 rows x 8 granules
            uint32_t dst = (uint32_t)__cvta_generic_to_shared(
                dB + r * 128 + ((g ^ (r & 7)) << 4));
            CP16(dst, W1t + (size_t)r * 256 + kc + g * 4);
        }
        CPCOMMIT();
    };

    stage1(0, 0);
    for (int c = 0; c < 8; c++) {
        if (c + 1 < 8) { stage1((c + 1) * 32, (c + 1) & 1); CPWAIT(1); }
        else           { CPWAIT(0); }
        __syncthreads();
        const float* As = (const float*)(sm + FSA + (c & 1) * 16384);
        const float* Bs = (const float*)(sm + FSB + (c & 1) * 32768);
#pragma unroll
        for (int ks = 0; ks < 32; ks += 8) {
            const int g0 = ks >> 2;
            uint32_t af[2][4], bf[4][2];
#pragma unroll
            for (int mi = 0; mi < 2; mi++) {
                int ra = wm * 32 + mi * 16 + qr;
                int sw = (ra & 7);
                const float* pa  = As + ra * 32;
                const float* pa8 = pa + 8 * 32;
                af[mi][0] = __float_as_uint(pa [((g0 ^ sw) << 2) + qc]);
                af[mi][1] = __float_as_uint(pa8[((g0 ^ sw) << 2) + qc]);
                af[mi][2] = __float_as_uint(pa [(((g0 + 1) ^ sw) << 2) + qc]);
                af[mi][3] = __float_as_uint(pa8[(((g0 + 1) ^ sw) << 2) + qc]);
            }
#pragma unroll
            for (int ni = 0; ni < 4; ni++) {
                int rb = wn * 32 + ni * 8 + qr;
                int sw = (rb & 7);
                const float* pb = Bs + rb * 32;
                bf[ni][0] = __float_as_uint(pb[((g0 ^ sw) << 2) + qc]);
                bf[ni][1] = __float_as_uint(pb[(((g0 + 1) ^ sw) << 2) + qc]);
            }
#pragma unroll
            for (int mi = 0; mi < 2; mi++)
#pragma unroll
                for (int ni = 0; ni < 4; ni++) MMA_TF32(acc[mi][ni], af[mi], bf[ni]);
        }
        __syncthreads();
    }

    // ---- phase-1 epilogue: bias + ELU + tf32 round -> swizzled h in smem ----
#pragma unroll
    for (int mi = 0; mi < 2; mi++) {
        int r = wm * 32 + mi * 16 + qr;
        int sw = (r & 7);               // (r+8)&7 == r&7
#pragma unroll
        for (int ni = 0; ni < 4; ni++) {
            int cb = wn * 32 + ni * 8 + qc * 2;
            float b0 = bias1[cb], b1v = bias1[cb + 1];
            float v0 = acc[mi][ni][0] + b0, v1 = acc[mi][ni][1] + b1v;
            float v2 = acc[mi][ni][2] + b0, v3 = acc[mi][ni][3] + b1v;
            v0 = (v0 > 0.f) ? v0 : expm1f(v0);
            v1 = (v1 > 0.f) ? v1 : expm1f(v1);
            v2 = (v2 > 0.f) ? v2 : expm1f(v2);
            v3 = (v3 > 0.f) ? v3 : expm1f(v3);
            int gg = cb >> 2, go = cb & 3;
            float* hp  = hbuf + r * 256 + ((gg ^ sw) << 2) + go;
            float* hp8 = hp + 8 * 256;
            hp [0] = __uint_as_float(cvt_tf32(v0));
            hp [1] = __uint_as_float(cvt_tf32(v1));
            hp8[0] = __uint_as_float(cvt_tf32(v2));
            hp8[1] = __uint_as_float(cvt_tf32(v3));
            acc[mi][ni][0] = 0.f; acc[mi][ni][1] = 0.f;
            acc[mi][ni][2] = 0.f; acc[mi][ni][3] = 0.f;
        }
    }
    __syncthreads();

    // ---- phase 2: out = h @ W2t^T + b2, A from smem h, B staged ----
    auto stage2 = [&](int kc, int s) {
        char* dB = sm + FSB + s * 32768;
#pragma unroll
        for (int i = 0; i < 2; i++) {
            int gid = tid + 1024 * i;
            int r = gid >> 3, g = gid & 7;
            uint32_t dst = (uint32_t)__cvta_generic_to_shared(
                dB + r * 128 + ((g ^ (r & 7)) << 4));
            CP16(dst, W2t + (size_t)r * 256 + kc + g * 4);
        }
        CPCOMMIT();
    };

    stage2(0, 0);
    for (int c = 0; c < 8; c++) {
        if (c + 1 < 8) { stage2((c + 1) * 32, (c + 1) & 1); CPWAIT(1); }
        else           { CPWAIT(0); }
        __syncthreads();
        const float* Bs = (const float*)(sm + FSB + (c & 1) * 32768);
#pragma unroll
        for (int ks = 0; ks < 32; ks += 8) {
            const int g0 = (c * 32 + ks) >> 2;   // h granule (0..62)
            const int g0l = ks >> 2;             // staged-B granule (0..7)
            uint32_t af[2][4], bf[4][2];
#pragma unroll
            for (int mi = 0; mi < 2; mi++) {
                int ra = wm * 32 + mi * 16 + qr;
                int sw = (ra & 7);
                const float* pa  = hbuf + ra * 256;
                const float* pa8 = pa + 8 * 256;
                af[mi][0] = __float_as_uint(pa [((g0 ^ sw) << 2) + qc]);
                af[mi][1] = __float_as_uint(pa8[((g0 ^ sw) << 2) + qc]);
                af[mi][2] = __float_as_uint(pa [(((g0 + 1) ^ sw) << 2) + qc]);
                af[mi][3] = __float_as_uint(pa8[(((g0 + 1) ^ sw) << 2) + qc]);
            }
#pragma unroll
            for (int ni = 0; ni < 4; ni++) {
                int rb = wn * 32 + ni * 8 + qr;
                int sw = (rb & 7);
                const float* pb = Bs + rb * 32;
                bf[ni][0] = __float_as_uint(pb[((g0l ^ sw) << 2) + qc]);
                bf[ni][1] = __float_as_uint(pb[(((g0l + 1) ^ sw) << 2) + qc]);
            }
#pragma unroll
            for (int mi = 0; mi < 2; mi++)
#pragma unroll
                for (int ni = 0; ni < 4; ni++) MMA_TF32(acc[mi][ni], af[mi], bf[ni]);
        }
        __syncthreads();
    }

    // ---- phase-2 epilogue: bias + store to gmem ----
#pragma unroll
    for (int mi = 0; mi < 2; mi++) {
        int r0 = row0 + wm * 32 + mi * 16 + qr;
#pragma unroll
        for (int ni = 0; ni < 4; ni++) {
            int cb = wn * 32 + ni * 8 + qc * 2;
            float b0 = bias2[cb], b1v = bias2[cb + 1];
            if (r0 < nrows)
                *(float2*)(Cout + (size_t)r0 * 256 + cb) =
                    make_float2(acc[mi][ni][0] + b0, acc[mi][ni][1] + b1v);
            if (r0 + 8 < nrows)
                *(float2*)(Cout + (size_t)(r0 + 8) * 256 + cb) =
                    make_float2(acc[mi][ni][2] + b0, acc[mi][ni][3] + b1v);
        }
    }
}

// ---------------- LSTM gates GEMM (fp32, split-K=2) — known good -------------
__global__ __launch_bounds__(256) void k_gates(
    const float* __restrict__ xin, int KW,
    const float* __restrict__ hold,
    const float* __restrict__ Wih, const float* __restrict__ Whh,
    float* __restrict__ gpart)
{
    __shared__ float a_s[32][33];
    __shared__ float w_s[32][33];
    const int tid = threadIdx.x;
    const int b0 = blockIdx.x * 32, j0 = blockIdx.y * 32;
    const int KT = KW + H_;
    const int khalf = KT >> 1;
    const int kbeg = blockIdx.z * khalf, kend = kbeg + khalf;
    const int ty = tid >> 4, tx = tid & 15;
    const int lr = tid >> 3, lc = (tid & 7) * 4;
    float a00 = 0.f, a01 = 0.f, a10 = 0.f, a11 = 0.f;

    for (int kt = kbeg; kt < kend; kt += 32) {
        const float *As, *Ws; int k, str;
        if (kt < KW) { As = xin;  Ws = Wih; k = kt;      str = KW; }
        else         { As = hold; Ws = Whh; k = kt - KW; str = H_; }
        float4 av = *(const float4*)(As + (size_t)(b0 + lr) * str + k + lc);
        a_s[lr][lc + 0] = av.x; a_s[lr][lc + 1] = av.y;
        a_s[lr][lc + 2] = av.z; a_s[lr][lc + 3] = av.w;
        float4 wv = *(const float4*)(Ws + (size_t)(j0 + lr) * str + k + lc);
        w_s[lr][lc + 0] = wv.x; w_s[lr][lc + 1] = wv.y;
        w_s[lr][lc + 2] = wv.z; w_s[lr][lc + 3] = wv.w;
        __syncthreads();
#pragma unroll
        for (int kk = 0; kk < 32; kk++) {
            float x0 = a_s[ty][kk], x1 = a_s[ty + 16][kk];
            float w0 = w_s[tx][kk], w1 = w_s[tx + 16][kk];
            a00 += x0 * w0; a01 += x0 * w1;
            a10 += x1 * w0; a11 += x1 * w1;
        }
        __syncthreads();
    }
    float* gp = gpart + (size_t)blockIdx.z * (B_ * 4 * H_);
    gp[(size_t)(b0 + ty)      * 1024 + j0 + tx]      = a00;
    gp[(size_t)(b0 + ty)      * 1024 + j0 + tx + 16] = a01;
    gp[(size_t)(b0 + ty + 16) * 1024 + j0 + tx]      = a10;
    gp[(size_t)(b0 + ty + 16) * 1024 + j0 + tx + 16] = a11;
}

// ---------------- LSTM cell elementwise ----------------
__device__ __forceinline__ float sigf(float x) { return 1.f / (1.f + expf(-x)); }

__global__ void k_update(const float* __restrict__ gp0, const float* __restrict__ gp1,
                         const float* __restrict__ bih, const float* __restrict__ bhh,
                         float* __restrict__ c, float* __restrict__ hnew,
                         float* __restrict__ qdst)
{
    int b = blockIdx.x, j = threadIdx.x;
    size_t g0 = (size_t)b * 1024;
    float iv = gp0[g0 + j]       + gp1[g0 + j]       + bih[j]       + bhh[j];
    float fv = gp0[g0 + 256 + j] + gp1[g0 + 256 + j] + bih[256 + j] + bhh[256 + j];
    float gv = gp0[g0 + 512 + j] + gp1[g0 + 512 + j] + bih[512 + j] + bhh[512 + j];
    float ov = gp0[g0 + 768 + j] + gp1[g0 + 768 + j] + bih[768 + j] + bhh[768 + j];
    float cn = sigf(fv) * c[b * H_ + j] + sigf(iv) * tanhf(gv);
    c[b * H_ + j] = cn;
    float hn = sigf(ov) * tanhf(cn);
    hnew[b * H_ + j] = hn;
    if (qdst) qdst[b * 2 * H_ + j] = hn;
}

// ---------------- attention partials: grid (B, P_), online softmax -----------
__global__ __launch_bounds__(512) void k_attn_part(
    const float* __restrict__ hfeat, const float* __restrict__ q)
{
    const int b = blockIdx.x, part = blockIdx.y, tid = threadIdx.x;
    const int g0 = g_seg[b], g1 = g_seg[b + 1];
    const int len = g1 - g0;
    const int s0 = g0 + (int)(((long long)len * part) / P_);
    const int s1 = g0 + (int)(((long long)len * (part + 1)) / P_);

    __shared__ float q_s[256];
    __shared__ float e_s[2][128];
    __shared__ float ws[2][128];
    __shared__ float racc[256];
    __shared__ float red[16];
    if (tid < 256) q_s[tid] = q[b * 256 + tid];
    __syncthreads();

    const int lane = tid & 31, warp = tid >> 5;
    const int col = tid & 255, half = tid >> 8;
    float qreg[8];
#pragma unroll
    for (int k = 0; k < 8; k++) qreg[k] = q_s[lane + 32 * k];

    float acc = 0.f, dpart = 0.f, m = -INFINITY;
    int buf = 0;

    for (int c0 = s0; c0 < s1; c0 += 128, buf ^= 1) {
        const int cnt = min(128, s1 - c0);
#pragma unroll
        for (int i = 0; i < 8; i++) {
            int nl = warp * 8 + i;
            if (nl < cnt) {
                const float* hr = hfeat + (size_t)(c0 + nl) * 256;
                float p = 0.f;
#pragma unroll
                for (int k = 0; k < 8; k++) p += hr[lane + 32 * k] * qreg[k];
#pragma unroll
                for (int off = 16; off; off >>= 1) p += __shfl_xor_sync(0xffffffffu, p, off);
                if (lane == 0) e_s[buf][nl] = p;
            }
        }
        __syncthreads();
        float v = -INFINITY;
#pragma unroll
        for (int j = 0; j < 4; j++) {
            int idx = lane + 32 * j;
            if (idx < cnt) v = fmaxf(v, e_s[buf][idx]);
        }
#pragma unroll
        for (int off = 16; off; off >>= 1)
            v = fmaxf(v, __shfl_xor_sync(0xffffffffu, v, off));
        const float mnew = fmaxf(m, v);
        const float scale = expf(m - mnew);
        acc *= scale; dpart *= scale; m = mnew;
        if (tid < cnt) {
            float wv = expf(e_s[buf][tid] - mnew);
            ws[buf][tid] = wv;
            dpart += wv;
        }
        __syncthreads();
        const int i0 = half * 64;
        const int i1 = min(cnt, i0 + 64);
        const float* bp = hfeat + ((size_t)c0 + i0) * 256 + col;
        const float* wp = ws[buf] + i0;
        if (i1 - i0 == 64) {
            float t0 = 0.f, t1 = 0.f, t2 = 0.f, t3 = 0.f;
#pragma unroll
            for (int i = 0; i < 64; i += 4) {
                t0 += wp[i]     * bp[(size_t)i * 256];
                t1 += wp[i + 1] * bp[(size_t)(i + 1) * 256];
                t2 += wp[i + 2] * bp[(size_t)(i + 2) * 256];
                t3 += wp[i + 3] * bp[(size_t)(i + 3) * 256];
            }
            acc += (t0 + t1) + (t2 + t3);
        } else {
            for (int i = 0; i < i1 - i0; i++) acc += wp[i] * bp[(size_t)i * 256];
        }
    }

    float d = dpart;
#pragma unroll
    for (int off = 16; off; off >>= 1) d += __shfl_xor_sync(0xffffffffu, d, off);
    if (lane == 0) red[warp] = d;
    if (half == 0) racc[col] = acc;
    __syncthreads();
    const int idx = b * P_ + part;
    if (tid == 0) {
        float s = 0.f;
        for (int i = 0; i < 16; i++) s += red[i];
        g_att_d[idx] = s;
        g_att_m[idx] = m;
    }
    if (half == 1) g_att_acc[(size_t)idx * 256 + col] = racc[col] + acc;
}

// ---------------- attention combine ----------------
__global__ __launch_bounds__(256) void k_attn_comb(float* __restrict__ qstar)
{
    const int b = blockIdx.x, col = threadIdx.x;
    __shared__ float sc[P_];
    __shared__ float sdenom;
    if (col == 0) {
        float m = -INFINITY;
#pragma unroll
        for (int p = 0; p < P_; p++) m = fmaxf(m, g_att_m[b * P_ + p]);
        if (!isfinite(m)) m = 0.f;
        float denom = 0.f;
#pragma unroll
        for (int p = 0; p < P_; p++) {
            float e = expf(g_att_m[b * P_ + p] - m);
            sc[p] = e;
            denom += g_att_d[b * P_ + p] * e;
        }
        sdenom = denom + 1e-16f;
    }
    __syncthreads();
    float r = 0.f;
#pragma unroll
    for (int p = 0; p < P_; p++)
        r += sc[p] * g_att_acc[(size_t)(b * P_ + p) * 256 + col];
    qstar[b * 2 * H_ + 256 + col] = r / sdenom;
}

// ---------------- output projection ----------------
__global__ void k_out(const float* __restrict__ qstar, const float* __restrict__ W,
                      const float* __restrict__ bias, float* __restrict__ out)
{
    int b = blockIdx.x, e = threadIdx.x;
    __shared__ float qs[512];
    qs[e] = qstar[b * 512 + e];
    qs[e + 128] = qstar[b * 512 + e + 128];
    qs[e + 256] = qstar[b * 512 + e + 256];
    qs[e + 384] = qstar[b * 512 + e + 384];
    __syncthreads();
    float acc = bias[e];
#pragma unroll 8
    for (int k = 0; k < 512; k++) acc += qs[k] * W[k * E_ + e];
    out[b * E_ + e] = acc;
}

// ---------------- launch ----------------
extern "C" void kernel_launch(void* const* d_in, const int* in_sizes, int n_in,
                              void* d_out, int out_size)
{
    const float* x    = (const float*)d_in[0];
    const int*   bidx = (const int*)d_in[1];
    const float* W1   = (const float*)d_in[2];
    const float* b1   = (const float*)d_in[3];
    const float* W2   = (const float*)d_in[4];
    const float* b2   = (const float*)d_in[5];
    const float* Wih[3] = {(const float*)d_in[6],  (const float*)d_in[10], (const float*)d_in[14]};
    const float* Whh[3] = {(const float*)d_in[7],  (const float*)d_in[11], (const float*)d_in[15]};
    const float* bih[3] = {(const float*)d_in[8],  (const float*)d_in[12], (const float*)d_in[16]};
    const float* bhh[3] = {(const float*)d_in[9],  (const float*)d_in[13], (const float*)d_in[17]};
    const float* outW = (const float*)d_in[18];
    const float* outb = (const float*)d_in[19];
    float* out = (float*)d_out;

    const int N = in_sizes[0] / D_;

    float *hfeat_p, *gpart_p, *hbuf_p, *c_p, *qstar_p, *wt1_p, *wt2_p;
    cudaGetSymbolAddress((void**)&hfeat_p, g_hfeat);
    cudaGetSymbolAddress((void**)&gpart_p, g_gpart);
    cudaGetSymbolAddress((void**)&hbuf_p,  g_hbuf);
    cudaGetSymbolAddress((void**)&c_p,     g_c);
    cudaGetSymbolAddress((void**)&qstar_p, g_qstar);
    cudaGetSymbolAddress((void**)&wt1_p,   g_Wt1);
    cudaGetSymbolAddress((void**)&wt2_p,   g_Wt2);

    cudaFuncSetAttribute(k_fnn_fused, cudaFuncAttributeMaxDynamicSharedMemorySize, FSMEM);

    k_initseg<<<257, 256>>>(bidx, N);
    dim3 tb(32, 32);
    dim3 tg(8, 8, 2);
    k_transpose<<<tg, tb>>>(W1, W2, wt1_p, wt2_p);

    k_fnn_fused<<<(N + 127) / 128, 1024, FSMEM>>>(x, wt1_p, wt2_p, b1, b2, hfeat_p, N);

    for (int s = 0; s < STEPS_; s++) {
        float* hold = hbuf_p + (size_t)(s & 1) * 3 * B_ * H_;
        float* hnew = hbuf_p + (size_t)((s & 1) ^ 1) * 3 * B_ * H_;
        for (int l = 0; l < 3; l++) {
            const float* xin = (l == 0) ? (const float*)qstar_p
                                        : (const float*)(hnew + (size_t)(l - 1) * B_ * H_);
            int KW = (l == 0) ? 2 * H_ : H_;
            dim3 gg(B_ / 32, 4 * H_ / 32, 2);
            k_gates<<<gg, 256>>>(xin, KW, hold + (size_t)l * B_ * H_,
                                 Wih[l], Whh[l], gpart_p);
            k_update<<<B_, H_>>>(gpart_p, gpart_p + (size_t)B_ * 4 * H_,
                                 bih[l], bhh[l],
                                 c_p + (size_t)l * B_ * H_,
                                 hnew + (size_t)l * B_ * H_,
                                 (l == 2) ? qstar_p : nullptr);
        }
        dim3 ag(B_, P_);
        k_attn_part<<<ag, 512>>>(hfeat_p, hnew + (size_t)2 * B_ * H_);
        k_attn_comb<<<B_, 256>>>(qstar_p);
    }
    k_out<<<B_, E_>>>(qstar_p, outW, outb, out);
}

// round 12
// speedup vs baseline: 1.1674x; 1.1674x over previous
#include <cuda_runtime.h>
#include <math.h>
#include <stdint.h>

#define D_ 256
#define H_ 256
#define B_ 128
#define E_ 128
#define STEPS_ 5
#define NMAX 100352
#define P_ 8            // attention partials per segment
#define ZK 4            // gates split-K factor
#define GP (B_ * 4 * H_)

// ---------------- scratch ----------------
__device__ __align__(16) float g_hfeat[NMAX * H_];
__device__ __align__(16) float g_gpart[ZK * GP];
__device__ float g_hbuf[2][3][B_ * H_];
__device__ float g_c[3][B_ * H_];
__device__ float g_qstar[B_ * 2 * H_];
__device__ int   g_seg[B_ + 1];
__device__ __align__(16) float g_Wt1[D_ * H_];
__device__ __align__(16) float g_Wt2[H_ * H_];
__device__ float g_att_m[B_ * P_];
__device__ float g_att_d[B_ * P_];
__device__ __align__(16) float g_att_acc[B_ * P_ * H_];
// concatenated [Wih|Whh] hi/lo per layer: l0 K=768, l1/l2 K=512
#define WO0 0
#define WO1 786432
#define WO2 1310720
#define WTOT 1835008
__device__ __align__(16) float g_Whi[WTOT];
__device__ __align__(16) float g_Wlo[WTOT];

__device__ __forceinline__ uint32_t cvt_tf32(float f) {
    uint32_t r;
    asm("cvt.rn.tf32.f32 %0, %1;" : "=r"(r) : "f"(f));
    return r;
}

#define CP16(dst, src) \
    asm volatile("cp.async.cg.shared.global [%0], [%1], 16;" :: "r"(dst), "l"(src) : "memory")
#define CPCOMMIT() asm volatile("cp.async.commit_group;" ::: "memory")
#define CPWAIT(n)  asm volatile("cp.async.wait_group %0;" :: "n"(n) : "memory")

#define MMA_TF32(d, a, b) \
    asm volatile( \
        "mma.sync.aligned.m16n8k8.row.col.f32.tf32.tf32.f32 " \
        "{%0,%1,%2,%3}, {%4,%5,%6,%7}, {%8,%9}, {%0,%1,%2,%3};" \
        : "+f"((d)[0]), "+f"((d)[1]), "+f"((d)[2]), "+f"((d)[3]) \
        : "r"((a)[0]), "r"((a)[1]), "r"((a)[2]), "r"((a)[3]), \
          "r"((b)[0]), "r"((b)[1]))

// ---------------- init + segment offsets (merged) ----------------
__global__ void k_initseg(const int* __restrict__ idx, int N) {
    if (blockIdx.x == 0) {
        int b = threadIdx.x;
        if (b <= B_) {
            int lo = 0, hi = N;
            while (lo < hi) {
                int mid = (lo + hi) >> 1;
                if (idx[mid] < b) lo = mid + 1; else hi = mid;
            }
            g_seg[b] = lo;
        }
    } else {
        int i = (blockIdx.x - 1) * blockDim.x + threadIdx.x;
        int stride = (gridDim.x - 1) * blockDim.x;
        for (int j = i; j < B_ * 2 * H_; j += stride) g_qstar[j] = 0.f;
        for (int j = i; j < 3 * B_ * H_; j += stride) {
            g_hbuf[0][0][j] = 0.f;
            g_hbuf[1][0][j] = 0.f;
            g_c[0][j] = 0.f;
        }
    }
}

// ---------------- weight transpose + tf32 round (FNN weights) ----------------
__global__ void k_transpose(const float* __restrict__ W1, const float* __restrict__ W2,
                            float* __restrict__ Wt1, float* __restrict__ Wt2) {
    __shared__ float t[32][33];
    const float* W  = blockIdx.z ? W2  : W1;
    float*       Wt = blockIdx.z ? Wt2 : Wt1;
    int bx = blockIdx.x * 32, by = blockIdx.y * 32;
    int tx = threadIdx.x, ty = threadIdx.y;
    t[ty][tx] = W[(by + ty) * 256 + bx + tx];
    __syncthreads();
    Wt[(bx + ty) * 256 + by + tx] = __uint_as_float(cvt_tf32(t[tx][ty]));
}

// ---------------- LSTM weight split: [Wih|Whh] -> hi/lo tf32 pair ------------
__global__ void k_wsplit(const float* __restrict__ Wih, const float* __restrict__ Whh,
                         int KW, float* __restrict__ Whi, float* __restrict__ Wlo) {
    const int K = KW + 256;
    const int total = 1024 * K;
    for (int i = blockIdx.x * blockDim.x + threadIdx.x; i < total;
         i += gridDim.x * blockDim.x) {
        int n = i / K, k = i - n * K;
        float v = (k < KW) ? Wih[n * KW + k] : Whh[n * 256 + (k - KW)];
        float h = __uint_as_float(cvt_tf32(v));
        Whi[i] = h;
        Wlo[i] = __uint_as_float(cvt_tf32(v - h));
    }
}

// ---------------- fused FNN (R8 512-thread version, known good) --------------
#define FH 0
#define FSA 131072
#define FSB 163840
#define FSMEM 229376

__global__ __launch_bounds__(512) void k_fnn_fused(
    const float* __restrict__ X, const float* __restrict__ W1t,
    const float* __restrict__ W2t, const float* __restrict__ b1,
    const float* __restrict__ b2, float* __restrict__ Cout, int nrows)
{
    extern __shared__ char sm[];
    float* hbuf = (float*)(sm + FH);
    __shared__ float bias1[256];
    __shared__ float bias2[256];

    const int tid  = threadIdx.x;
    const int lane = tid & 31;
    const int warp = tid >> 5;
    const int wm = warp & 3;
    const int wn = warp >> 2;
    const int qr = lane >> 2;
    const int qc = lane & 3;
    const int row0 = blockIdx.x * 128;

    if (tid < 256) bias1[tid] = b1[tid];
    else           bias2[tid - 256] = b2[tid - 256];

    float acc[2][8][4];
#pragma unroll
    for (int mi = 0; mi < 2; mi++)
#pragma unroll
        for (int ni = 0; ni < 8; ni++)
#pragma unroll
            for (int j = 0; j < 4; j++) acc[mi][ni][j] = 0.f;

    auto stage1 = [&](int kc, int s) {
        char* dA = sm + FSA + s * 16384;
        char* dB = sm + FSB + s * 32768;
#pragma unroll
        for (int i = 0; i < 2; i++) {
            int gid = tid + 512 * i;
            int r = gid >> 3, g = gid & 7;
            int gr = row0 + r; if (gr >= nrows) gr = nrows - 1;
            uint32_t dst = (uint32_t)__cvta_generic_to_shared(
                dA + r * 128 + ((g ^ (r & 7)) << 4));
            CP16(dst, X + (size_t)gr * 256 + kc + g * 4);
        }
#pragma unroll
        for (int i = 0; i < 4; i++) {
            int gid = tid + 512 * i;
            int r = gid >> 3, g = gid & 7;
            uint32_t dst = (uint32_t)__cvta_generic_to_shared(
                dB + r * 128 + ((g ^ (r & 7)) << 4));
            CP16(dst, W1t + (size_t)r * 256 + kc + g * 4);
        }
        CPCOMMIT();
    };

    stage1(0, 0);
    for (int c = 0; c < 8; c++) {
        if (c + 1 < 8) { stage1((c + 1) * 32, (c + 1) & 1); CPWAIT(1); }
        else           { CPWAIT(0); }
        __syncthreads();
        const float* As = (const float*)(sm + FSA + (c & 1) * 16384);
        const float* Bs = (const float*)(sm + FSB + (c & 1) * 32768);
#pragma unroll
        for (int ks = 0; ks < 32; ks += 8) {
            const int g0 = ks >> 2;
            uint32_t af[2][4], bf[8][2];
#pragma unroll
            for (int mi = 0; mi < 2; mi++) {
                int ra = wm * 32 + mi * 16 + qr;
                int sw = (ra & 7);
                const float* pa  = As + ra * 32;
                const float* pa8 = pa + 8 * 32;
                af[mi][0] = __float_as_uint(pa [((g0 ^ sw) << 2) + qc]);
                af[mi][1] = __float_as_uint(pa8[((g0 ^ sw) << 2) + qc]);
                af[mi][2] = __float_as_uint(pa [(((g0 + 1) ^ sw) << 2) + qc]);
                af[mi][3] = __float_as_uint(pa8[(((g0 + 1) ^ sw) << 2) + qc]);
            }
#pragma unroll
            for (int ni = 0; ni < 8; ni++) {
                int rb = wn * 64 + ni * 8 + qr;
                int sw = (rb & 7);
                const float* pb = Bs + rb * 32;
                bf[ni][0] = __float_as_uint(pb[((g0 ^ sw) << 2) + qc]);
                bf[ni][1] = __float_as_uint(pb[(((g0 + 1) ^ sw) << 2) + qc]);
            }
#pragma unroll
            for (int mi = 0; mi < 2; mi++)
#pragma unroll
                for (int ni = 0; ni < 8; ni++) MMA_TF32(acc[mi][ni], af[mi], bf[ni]);
        }
        __syncthreads();
    }

#pragma unroll
    for (int mi = 0; mi < 2; mi++) {
        int r = wm * 32 + mi * 16 + qr;
        int sw = (r & 7);
#pragma unroll
        for (int ni = 0; ni < 8; ni++) {
            int cb = wn * 64 + ni * 8 + qc * 2;
            float b0 = bias1[cb], b1v = bias1[cb + 1];
            float v0 = acc[mi][ni][0] + b0, v1 = acc[mi][ni][1] + b1v;
            float v2 = acc[mi][ni][2] + b0, v3 = acc[mi][ni][3] + b1v;
            v0 = (v0 > 0.f) ? v0 : expm1f(v0);
            v1 = (v1 > 0.f) ? v1 : expm1f(v1);
            v2 = (v2 > 0.f) ? v2 : expm1f(v2);
            v3 = (v3 > 0.f) ? v3 : expm1f(v3);
            int gg = cb >> 2, go = cb & 3;
            float* hp  = hbuf + r * 256 + ((gg ^ sw) << 2) + go;
            float* hp8 = hp + 8 * 256;
            hp [0] = __uint_as_float(cvt_tf32(v0));
            hp [1] = __uint_as_float(cvt_tf32(v1));
            hp8[0] = __uint_as_float(cvt_tf32(v2));
            hp8[1] = __uint_as_float(cvt_tf32(v3));
            acc[mi][ni][0] = 0.f; acc[mi][ni][1] = 0.f;
            acc[mi][ni][2] = 0.f; acc[mi][ni][3] = 0.f;
        }
    }
    __syncthreads();

    auto stage2 = [&](int kc, int s) {
        char* dB = sm + FSB + s * 32768;
#pragma unroll
        for (int i = 0; i < 4; i++) {
            int gid = tid + 512 * i;
            int r = gid >> 3, g = gid & 7;
            uint32_t dst = (uint32_t)__cvta_generic_to_shared(
                dB + r * 128 + ((g ^ (r & 7)) << 4));
            CP16(dst, W2t + (size_t)r * 256 + kc + g * 4);
        }
        CPCOMMIT();
    };

    stage2(0, 0);
    for (int c = 0; c < 8; c++) {
        if (c + 1 < 8) { stage2((c + 1) * 32, (c + 1) & 1); CPWAIT(1); }
        else           { CPWAIT(0); }
        __syncthreads();
        const float* Bs = (const float*)(sm + FSB + (c & 1) * 32768);
#pragma unroll
        for (int ks = 0; ks < 32; ks += 8) {
            const int g0 = (c * 32 + ks) >> 2;
            const int g0l = ks >> 2;
            uint32_t af[2][4], bf[8][2];
#pragma unroll
            for (int mi = 0; mi < 2; mi++) {
                int ra = wm * 32 + mi * 16 + qr;
                int sw = (ra & 7);
                const float* pa  = hbuf + ra * 256;
                const float* pa8 = pa + 8 * 256;
                af[mi][0] = __float_as_uint(pa [((g0 ^ sw) << 2) + qc]);
                af[mi][1] = __float_as_uint(pa8[((g0 ^ sw) << 2) + qc]);
                af[mi][2] = __float_as_uint(pa [(((g0 + 1) ^ sw) << 2) + qc]);
                af[mi][3] = __float_as_uint(pa8[(((g0 + 1) ^ sw) << 2) + qc]);
            }
#pragma unroll
            for (int ni = 0; ni < 8; ni++) {
                int rb = wn * 64 + ni * 8 + qr;
                int sw = (rb & 7);
                const float* pb = Bs + rb * 32;
                bf[ni][0] = __float_as_uint(pb[((g0l ^ sw) << 2) + qc]);
                bf[ni][1] = __float_as_uint(pb[(((g0l + 1) ^ sw) << 2) + qc]);
            }
#pragma unroll
            for (int mi = 0; mi < 2; mi++)
#pragma unroll
                for (int ni = 0; ni < 8; ni++) MMA_TF32(acc[mi][ni], af[mi], bf[ni]);
        }
        __syncthreads();
    }

#pragma unroll
    for (int mi = 0; mi < 2; mi++) {
        int r0 = row0 + wm * 32 + mi * 16 + qr;
#pragma unroll
        for (int ni = 0; ni < 8; ni++) {
            int cb = wn * 64 + ni * 8 + qc * 2;
            float b0 = bias2[cb], b1v = bias2[cb + 1];
            if (r0 < nrows)
                *(float2*)(Cout + (size_t)r0 * 256 + cb) =
                    make_float2(acc[mi][ni][0] + b0, acc[mi][ni][1] + b1v);
            if (r0 + 8 < nrows)
                *(float2*)(Cout + (size_t)(r0 + 8) * 256 + cb) =
                    make_float2(acc[mi][ni][2] + b0, acc[mi][ni][3] + b1v);
        }
    }
}

// ---------------- LSTM gates via 3xTF32 HMMA ---------------------------------
// gates[128,1024] = [xin|hold] @ Wcat^T, split-K=ZK. Grid (16, ZK), 256 thr.
// Block tile M=128 x N=64, warps 2x4, warp tile 64x16. K chunks of 32.
// Buffer s (floats): A_hi s*12288, A_lo +4096, B_hi +8192, B_lo +10240.
#define GSM_BYTES 98304

__global__ __launch_bounds__(256) void k_gates_mma(
    const float* __restrict__ xin, int KW,
    const float* __restrict__ hold,
    const float* __restrict__ Whi, const float* __restrict__ Wlo, int K,
    float* __restrict__ gpart)
{
    extern __shared__ float gsm[];
    const int tid = threadIdx.x;
    const int lane = tid & 31, warp = tid >> 5;
    const int wm = warp & 1, wn = warp >> 1;     // 2 x 4
    const int qr = lane >> 2, qc = lane & 3;
    const int n0 = blockIdx.x * 64;
    const int z = blockIdx.y;
    const int kq = K >> 2;                       // K/ZK
    const int ko = z * kq;
    const int nc = kq >> 5;                      // chunks of 32

    float acc[4][2][4];
#pragma unroll
    for (int mi = 0; mi < 4; mi++)
#pragma unroll
        for (int ni = 0; ni < 2; ni++)
#pragma unroll
            for (int j = 0; j < 4; j++) acc[mi][ni][j] = 0.f;

    float4 ra[4];
    auto ldgA = [&](int kglob) {
#pragma unroll
        for (int i = 0; i < 4; i++) {
            int gid = tid + 256 * i;
            int r = gid >> 3, g = gid & 7;
            int k = kglob + g * 4;
            const float* src; int stride, kk;
            if (k < KW) { src = xin;  stride = KW;  kk = k; }
            else        { src = hold; stride = 256; kk = k - KW; }
            ra[i] = *(const float4*)(src + (size_t)r * stride + kk);
        }
    };
    auto stsA = [&](int s) {
        float* Ahi = gsm + s * 12288;
        float* Alo = Ahi + 4096;
#pragma unroll
        for (int i = 0; i < 4; i++) {
            int gid = tid + 256 * i;
            int r = gid >> 3, g = gid & 7;
            int off = r * 32 + ((g ^ (r & 7)) << 2);
            float4 v = ra[i];
            float h0 = __uint_as_float(cvt_tf32(v.x));
            float h1 = __uint_as_float(cvt_tf32(v.y));
            float h2 = __uint_as_float(cvt_tf32(v.z));
            float h3 = __uint_as_float(cvt_tf32(v.w));
            Ahi[off + 0] = h0; Ahi[off + 1] = h1;
            Ahi[off + 2] = h2; Ahi[off + 3] = h3;
            Alo[off + 0] = __uint_as_float(cvt_tf32(v.x - h0));
            Alo[off + 1] = __uint_as_float(cvt_tf32(v.y - h1));
            Alo[off + 2] = __uint_as_float(cvt_tf32(v.z - h2));
            Alo[off + 3] = __uint_as_float(cvt_tf32(v.w - h3));
        }
    };
    auto stageB = [&](int kglob, int s) {
        float* Bhi = gsm + s * 12288 + 8192;
        float* Blo = gsm + s * 12288 + 10240;
#pragma unroll
        for (int i = 0; i < 4; i++) {
            int gid = tid + 256 * i;             // 0..1023
            int hilo = gid >> 9;
            int rg = gid & 511;
            int r = rg >> 3, g = rg & 7;
            const float* src = (hilo ? Wlo : Whi) + (size_t)(n0 + r) * K + kglob + g * 4;
            float* dstb = hilo ? Blo : Bhi;
            uint32_t dst = (uint32_t)__cvta_generic_to_shared(
                dstb + r * 32 + ((g ^ (r & 7)) << 2));
            CP16(dst, src);
        }
        CPCOMMIT();
    };

    ldgA(ko);
    stageB(ko, 0);
    for (int c = 0; c < nc; c++) {
        const int s = c & 1;
        stsA(s);
        if (c + 1 < nc) {
            ldgA(ko + (c + 1) * 32);
            stageB(ko + (c + 1) * 32, s ^ 1);
            CPWAIT(1);
        } else {
            CPWAIT(0);
        }
        __syncthreads();
        const float* Ahi = gsm + s * 12288;
        const float* Alo = Ahi + 4096;
        const float* Bhi = Ahi + 8192;
        const float* Blo = Ahi + 10240;
#pragma unroll
        for (int ks = 0; ks < 32; ks += 8) {
            const int g0 = ks >> 2;
            uint32_t ah[4][4], al[4][4], bh[2][2], bl[2][2];
#pragma unroll
            for (int mi = 0; mi < 4; mi++) {
                int rr = wm * 64 + mi * 16 + qr;
                int sw = (rr & 7);
                int o0 = rr * 32 + ((g0 ^ sw) << 2) + qc;
                int o1 = rr * 32 + (((g0 + 1) ^ sw) << 2) + qc;
                ah[mi][0] = __float_as_uint(Ahi[o0]);
                ah[mi][1] = __float_as_uint(Ahi[o0 + 256]);   // +8 rows = +8*32
                ah[mi][2] = __float_as_uint(Ahi[o1]);
                ah[mi][3] = __float_as_uint(Ahi[o1 + 256]);
                al[mi][0] = __float_as_uint(Alo[o0]);
                al[mi][1] = __float_as_uint(Alo[o0 + 256]);
                al[mi][2] = __float_as_uint(Alo[o1]);
                al[mi][3] = __float_as_uint(Alo[o1 + 256]);
            }
#pragma unroll
            for (int ni = 0; ni < 2; ni++) {
                int rb = wn * 16 + ni * 8 + qr;
                int sw = (rb & 7);
                int o0 = rb * 32 + ((g0 ^ sw) << 2) + qc;
                int o1 = rb * 32 + (((g0 + 1) ^ sw) << 2) + qc;
                bh[ni][0] = __float_as_uint(Bhi[o0]);
                bh[ni][1] = __float_as_uint(Bhi[o1]);
                bl[ni][0] = __float_as_uint(Blo[o0]);
                bl[ni][1] = __float_as_uint(Blo[o1]);
            }
#pragma unroll
            for (int mi = 0; mi < 4; mi++)
#pragma unroll
                for (int ni = 0; ni < 2; ni++) {
                    MMA_TF32(acc[mi][ni], ah[mi], bh[ni]);
                    MMA_TF32(acc[mi][ni], ah[mi], bl[ni]);
                    MMA_TF32(acc[mi][ni], al[mi], bh[ni]);
                }
        }
        __syncthreads();
    }

    float* gp = gpart + (size_t)z * GP;
#pragma unroll
    for (int mi = 0; mi < 4; mi++) {
        int r = wm * 64 + mi * 16 + qr;
#pragma unroll
        for (int ni = 0; ni < 2; ni++) {
            int colb = n0 + wn * 16 + ni * 8 + qc * 2;
            *(float2*)(gp + (size_t)r * 1024 + colb) =
                make_float2(acc[mi][ni][0], acc[mi][ni][1]);
            *(float2*)(gp + (size_t)(r + 8) * 1024 + colb) =
                make_float2(acc[mi][ni][2], acc[mi][ni][3]);
        }
    }
}

// ---------------- LSTM cell elementwise (sums ZK partials) ----------------
__device__ __forceinline__ float sigf(float x) { return 1.f / (1.f + expf(-x)); }

__global__ void k_update(const float* __restrict__ gp,
                         const float* __restrict__ bih, const float* __restrict__ bhh,
                         float* __restrict__ c, float* __restrict__ hnew,
                         float* __restrict__ qdst)
{
    int b = blockIdx.x, j = threadIdx.x;
    size_t g0 = (size_t)b * 1024;
    float iv = bih[j] + bhh[j];
    float fv = bih[256 + j] + bhh[256 + j];
    float gv = bih[512 + j] + bhh[512 + j];
    float ov = bih[768 + j] + bhh[768 + j];
#pragma unroll
    for (int z = 0; z < ZK; z++) {
        const float* p = gp + (size_t)z * GP + g0;
        iv += p[j]; fv += p[256 + j]; gv += p[512 + j]; ov += p[768 + j];
    }
    float cn = sigf(fv) * c[b * H_ + j] + sigf(iv) * tanhf(gv);
    c[b * H_ + j] = cn;
    float hn = sigf(ov) * tanhf(cn);
    hnew[b * H_ + j] = hn;
    if (qdst) qdst[b * 2 * H_ + j] = hn;
}

// ---------------- attention partials: grid (B, P_), online softmax -----------
__global__ __launch_bounds__(512) void k_attn_part(
    const float* __restrict__ hfeat, const float* __restrict__ q)
{
    const int b = blockIdx.x, part = blockIdx.y, tid = threadIdx.x;
    const int g0 = g_seg[b], g1 = g_seg[b + 1];
    const int len = g1 - g0;
    const int s0 = g0 + (int)(((long long)len * part) / P_);
    const int s1 = g0 + (int)(((long long)len * (part + 1)) / P_);

    __shared__ float q_s[256];
    __shared__ float e_s[2][128];
    __shared__ float ws[2][128];
    __shared__ float racc[256];
    __shared__ float red[16];
    if (tid < 256) q_s[tid] = q[b * 256 + tid];
    __syncthreads();

    const int lane = tid & 31, warp = tid >> 5;
    const int col = tid & 255, half = tid >> 8;
    float qreg[8];
#pragma unroll
    for (int k = 0; k < 8; k++) qreg[k] = q_s[lane + 32 * k];

    float acc = 0.f, dpart = 0.f, m = -INFINITY;
    int buf = 0;

    for (int c0 = s0; c0 < s1; c0 += 128, buf ^= 1) {
        const int cnt = min(128, s1 - c0);
#pragma unroll
        for (int i = 0; i < 8; i++) {
            int nl = warp * 8 + i;
            if (nl < cnt) {
                const float* hr = hfeat + (size_t)(c0 + nl) * 256;
                float p = 0.f;
#pragma unroll
                for (int k = 0; k < 8; k++) p += hr[lane + 32 * k] * qreg[k];
#pragma unroll
                for (int off = 16; off; off >>= 1) p += __shfl_xor_sync(0xffffffffu, p, off);
                if (lane == 0) e_s[buf][nl] = p;
            }
        }
        __syncthreads();
        float v = -INFINITY;
#pragma unroll
        for (int j = 0; j < 4; j++) {
            int idx = lane + 32 * j;
            if (idx < cnt) v = fmaxf(v, e_s[buf][idx]);
        }
#pragma unroll
        for (int off = 16; off; off >>= 1)
            v = fmaxf(v, __shfl_xor_sync(0xffffffffu, v, off));
        const float mnew = fmaxf(m, v);
        const float scale = expf(m - mnew);
        acc *= scale; dpart *= scale; m = mnew;
        if (tid < cnt) {
            float wv = expf(e_s[buf][tid] - mnew);
            ws[buf][tid] = wv;
            dpart += wv;
        }
        __syncthreads();
        const int i0 = half * 64;
        const int i1 = min(cnt, i0 + 64);
        const float* bp = hfeat + ((size_t)c0 + i0) * 256 + col;
        const float* wp = ws[buf] + i0;
        if (i1 - i0 == 64) {
            float t0 = 0.f, t1 = 0.f, t2 = 0.f, t3 = 0.f;
#pragma unroll
            for (int i = 0; i < 64; i += 4) {
                t0 += wp[i]     * bp[(size_t)i * 256];
                t1 += wp[i + 1] * bp[(size_t)(i + 1) * 256];
                t2 += wp[i + 2] * bp[(size_t)(i + 2) * 256];
                t3 += wp[i + 3] * bp[(size_t)(i + 3) * 256];
            }
            acc += (t0 + t1) + (t2 + t3);
        } else {
            for (int i = 0; i < i1 - i0; i++) acc += wp[i] * bp[(size_t)i * 256];
        }
    }

    float d = dpart;
#pragma unroll
    for (int off = 16; off; off >>= 1) d += __shfl_xor_sync(0xffffffffu, d, off);
    if (lane == 0) red[warp] = d;
    if (half == 0) racc[col] = acc;
    __syncthreads();
    const int idx = b * P_ + part;
    if (tid == 0) {
        float s = 0.f;
        for (int i = 0; i < 16; i++) s += red[i];
        g_att_d[idx] = s;
        g_att_m[idx] = m;
    }
    if (half == 1) g_att_acc[(size_t)idx * 256 + col] = racc[col] + acc;
}

// ---------------- attention combine ----------------
__global__ __launch_bounds__(256) void k_attn_comb(float* __restrict__ qstar)
{
    const int b = blockIdx.x, col = threadIdx.x;
    __shared__ float sc[P_];
    __shared__ float sdenom;
    if (col == 0) {
        float m = -INFINITY;
#pragma unroll
        for (int p = 0; p < P_; p++) m = fmaxf(m, g_att_m[b * P_ + p]);
        if (!isfinite(m)) m = 0.f;
        float denom = 0.f;
#pragma unroll
        for (int p = 0; p < P_; p++) {
            float e = expf(g_att_m[b * P_ + p] - m);
            sc[p] = e;
            denom += g_att_d[b * P_ + p] * e;
        }
        sdenom = denom + 1e-16f;
    }
    __syncthreads();
    float r = 0.f;
#pragma unroll
    for (int p = 0; p < P_; p++)
        r += sc[p] * g_att_acc[(size_t)(b * P_ + p) * 256 + col];
    qstar[b * 2 * H_ + 256 + col] = r / sdenom;
}

// ---------------- output projection ----------------
__global__ void k_out(const float* __restrict__ qstar, const float* __restrict__ W,
                      const float* __restrict__ bias, float* __restrict__ out)
{
    int b = blockIdx.x, e = threadIdx.x;
    __shared__ float qs[512];
    qs[e] = qstar[b * 512 + e];
    qs[e + 128] = qstar[b * 512 + e + 128];
    qs[e + 256] = qstar[b * 512 + e + 256];
    qs[e + 384] = qstar[b * 512 + e + 384];
    __syncthreads();
    float acc = bias[e];
#pragma unroll 8
    for (int k = 0; k < 512; k++) acc += qs[k] * W[k * E_ + e];
    out[b * E_ + e] = acc;
}

// ---------------- launch ----------------
extern "C" void kernel_launch(void* const* d_in, const int* in_sizes, int n_in,
                              void* d_out, int out_size)
{
    const float* x    = (const float*)d_in[0];
    const int*   bidx = (const int*)d_in[1];
    const float* W1   = (const float*)d_in[2];
    const float* b1   = (const float*)d_in[3];
    const float* W2   = (const float*)d_in[4];
    const float* b2   = (const float*)d_in[5];
    const float* Wih[3] = {(const float*)d_in[6],  (const float*)d_in[10], (const float*)d_in[14]};
    const float* Whh[3] = {(const float*)d_in[7],  (const float*)d_in[11], (const float*)d_in[15]};
    const float* bih[3] = {(const float*)d_in[8],  (const float*)d_in[12], (const float*)d_in[16]};
    const float* bhh[3] = {(const float*)d_in[9],  (const float*)d_in[13], (const float*)d_in[17]};
    const float* outW = (const float*)d_in[18];
    const float* outb = (const float*)d_in[19];
    float* out = (float*)d_out;

    const int N = in_sizes[0] / D_;

    float *hfeat_p, *gpart_p, *hbuf_p, *c_p, *qstar_p, *wt1_p, *wt2_p, *whi_p, *wlo_p;
    cudaGetSymbolAddress((void**)&hfeat_p, g_hfeat);
    cudaGetSymbolAddress((void**)&gpart_p, g_gpart);
    cudaGetSymbolAddress((void**)&hbuf_p,  g_hbuf);
    cudaGetSymbolAddress((void**)&c_p,     g_c);
    cudaGetSymbolAddress((void**)&qstar_p, g_qstar);
    cudaGetSymbolAddress((void**)&wt1_p,   g_Wt1);
    cudaGetSymbolAddress((void**)&wt2_p,   g_Wt2);
    cudaGetSymbolAddress((void**)&whi_p,   g_Whi);
    cudaGetSymbolAddress((void**)&wlo_p,   g_Wlo);

    cudaFuncSetAttribute(k_fnn_fused, cudaFuncAttributeMaxDynamicSharedMemorySize, FSMEM);
    cudaFuncSetAttribute(k_gates_mma, cudaFuncAttributeMaxDynamicSharedMemorySize, GSM_BYTES);

    const int woff[3] = {WO0, WO1, WO2};
    const int klen[3] = {768, 512, 512};

    k_initseg<<<257, 256>>>(bidx, N);
    dim3 tb(32, 32);
    dim3 tg(8, 8, 2);
    k_transpose<<<tg, tb>>>(W1, W2, wt1_p, wt2_p);
    for (int l = 0; l < 3; l++)
        k_wsplit<<<256, 256>>>(Wih[l], Whh[l], klen[l] - 256,
                               whi_p + woff[l], wlo_p + woff[l]);

    k_fnn_fused<<<(N + 127) / 128, 512, FSMEM>>>(x, wt1_p, wt2_p, b1, b2, hfeat_p, N);

    for (int s = 0; s < STEPS_; s++) {
        float* hold = hbuf_p + (size_t)(s & 1) * 3 * B_ * H_;
        float* hnew = hbuf_p + (size_t)((s & 1) ^ 1) * 3 * B_ * H_;
        for (int l = 0; l < 3; l++) {
            const float* xin = (l == 0) ? (const float*)qstar_p
                                        : (const float*)(hnew + (size_t)(l - 1) * B_ * H_);
            int KW = klen[l] - 256;
            dim3 gg(16, ZK);
            k_gates_mma<<<gg, 256, GSM_BYTES>>>(xin, KW, hold + (size_t)l * B_ * H_,
                                                whi_p + woff[l], wlo_p + woff[l],
                                                klen[l], gpart_p);
            k_update<<<B_, H_>>>(gpart_p, bih[l], bhh[l],
                                 c_p + (size_t)l * B_ * H_,
                                 hnew + (size_t)l * B_ * H_,
                                 (l == 2) ? qstar_p : nullptr);
        }
        dim3 ag(B_, P_);
        k_attn_part<<<ag, 512>>>(hfeat_p, hnew + (size_t)2 * B_ * H_);
        k_attn_comb<<<B_, 256>>>(qstar_p);
    }
    k_out<<<B_, E_>>>(qstar_p, outW, outb, out);
}